// round 2
// baseline (speedup 1.0000x reference)
#include <cuda_runtime.h>

// Problem constants
#define TB 8192   // batch
#define TT 512    // seq len
#define DD 8      // input size
#define HH 64     // hidden
#define R  32     // batch rows per block
#define RP 36     // padded row stride (floats): 144B, 16B aligned, odd/4 for bank spread
#define NT 256    // threads per block (one per gate)

// Transposed-weight scratch: [k][256] layouts for all 12 matrices.
// enc: l0 ih(8x256)@0, l0 hh(64x256)@2048, l1 ih@18432, l1 hh@34816, l2 ih@51200, l2 hh@67584
// dec: l0 ih(72x256)@83968, l0 hh@102400, l1 ih@118784, l1 hh@135168, l2 ih@151552, l2 hh@167936
__device__ float g_wt[184320];

__global__ void transpose_w(const float* __restrict__ src, int dst_off, int cols) {
    int idx = blockIdx.x * blockDim.x + threadIdx.x;
    int n = cols * 256;
    if (idx < n) {
        int k = idx >> 8;
        int j = idx & 255;
        g_wt[dst_off + idx] = src[j * cols + k];
    }
}

__device__ __forceinline__ float sigf(float x) {
    // sig(-inf)->expf(+big)=inf -> 1/inf = 0 : safe, no NaN
    return __fdividef(1.f, 1.f + __expf(-x));
}
__device__ __forceinline__ float tanh_f(float x) {
    x = fminf(fmaxf(x, -20.f), 20.f);   // tanh(+-20) == +-1 in fp32; avoids inf/inf
    float e = __expf(-2.f * x);
    return __fdividef(1.f - e, 1.f + e);
}

// acc[r] += sum_k WT[k][j] * buf[k][r]   (buf is [K][RP] transposed staging)
__device__ __forceinline__ void gemv_accum(float acc[R], const float* __restrict__ WT,
                                           int K, const float* __restrict__ buf, int j) {
    #pragma unroll 2
    for (int k = 0; k < K; k++) {
        float w = WT[k * 256 + j];                        // coalesced LDG (L1/L2)
        const float4* xp = (const float4*)(buf + k * RP); // smem broadcast reads
        #pragma unroll
        for (int q = 0; q < 8; q++) {
            float4 v = xp[q];
            acc[4*q+0] = fmaf(w, v.x, acc[4*q+0]);
            acc[4*q+1] = fmaf(w, v.y, acc[4*q+1]);
            acc[4*q+2] = fmaf(w, v.z, acc[4*q+2]);
            acc[4*q+3] = fmaf(w, v.w, acc[4*q+3]);
        }
    }
}

__device__ __forceinline__ void update_states(const float* __restrict__ s_g,
                                              float* __restrict__ h_st,
                                              float* __restrict__ c_st,
                                              float* __restrict__ y_copy,
                                              int tid) {
    int u  = tid & 63;
    int r0 = (tid >> 6) * 8;
    #pragma unroll
    for (int rr = 0; rr < 8; rr++) {
        int r = r0 + rr;
        const float* gr = s_g + r * 256;
        float gi = gr[u];
        float gf = gr[64 + u];
        float gg = gr[128 + u];
        float go = gr[192 + u];
        float c = c_st[u * RP + r];
        c = sigf(gf) * c + sigf(gi) * tanh_f(gg);
        float h = sigf(go) * tanh_f(c);
        c_st[u * RP + r] = c;
        h_st[u * RP + r] = h;
        if (y_copy) y_copy[u * RP + r] = h;
    }
}

// One full LSTM layer for one timestep: gates gemv -> smem -> nonlinearity/state update.
// inbuf2/WTi2 optionally add a second input segment (decoder concat of y_prev).
__device__ __forceinline__ void layer_step(const float* __restrict__ WTi, int Ki,
                                           const float* __restrict__ inbuf,
                                           const float* __restrict__ WTi2,
                                           const float* __restrict__ inbuf2,
                                           const float* __restrict__ WTh,
                                           const float* __restrict__ hbuf,
                                           const float* __restrict__ bias,
                                           float* __restrict__ s_g,
                                           float* __restrict__ h_st,
                                           float* __restrict__ c_st,
                                           float* __restrict__ y_copy,
                                           int tid) {
    float acc[R];
    float bj = bias[tid];
    #pragma unroll
    for (int r = 0; r < R; r++) acc[r] = bj;
    gemv_accum(acc, WTi, Ki, inbuf, tid);
    if (inbuf2) gemv_accum(acc, WTi2, HH, inbuf2, tid);
    gemv_accum(acc, WTh, HH, hbuf, tid);
    #pragma unroll
    for (int r = 0; r < R; r++) s_g[r * 256 + tid] = acc[r];   // coalesced STS
    __syncthreads();
    update_states(s_g, h_st, c_st, y_copy, tid);
    __syncthreads();
}

__global__ __launch_bounds__(NT, 2)
void lstm_main(const float* __restrict__ enc_x, const float* __restrict__ dec_x,
               const float* __restrict__ eb0, const float* __restrict__ eb1,
               const float* __restrict__ eb2,
               const float* __restrict__ db0, const float* __restrict__ db1,
               const float* __restrict__ db2,
               const float* __restrict__ fcW, const float* __restrict__ fcb,
               float* __restrict__ out) {
    extern __shared__ float sm[];
    float* s_hs = sm;                     // 3 * 64 * RP  (h states, [l][u][r])
    float* s_cs = s_hs + 3 * HH * RP;     // 3 * 64 * RP  (c states)
    float* s_y  = s_cs + 3 * HH * RP;     // 64 * RP      (decoder y_prev, transposed)
    float* s_x  = s_y + HH * RP;          // 8 * RP       (x_t staging, transposed)
    float* s_g  = s_x + DD * RP;          // 32 * 256     (gates, [r][j])
    float* s_fc = s_g + R * 256;          // 64*8 fcW^T + 8 fcb

    int tid = threadIdx.x;
    int b0  = blockIdx.x * R;

    // zero h, c, y_prev (contiguous region)
    for (int i = tid; i < 3 * HH * RP * 2 + HH * RP; i += NT) sm[i] = 0.f;
    // stage fc weights transposed: s_fc[u*8+d] = fcW[d][u]
    for (int i = tid; i < DD * HH; i += NT) {
        int u = i >> 3, d = i & 7;
        s_fc[u * 8 + d] = fcW[d * HH + u];
    }
    if (tid < DD) s_fc[512 + tid] = fcb[tid];
    __syncthreads();

    const float* WT_e0i = g_wt;           const float* WT_e0h = g_wt + 2048;
    const float* WT_e1i = g_wt + 18432;   const float* WT_e1h = g_wt + 34816;
    const float* WT_e2i = g_wt + 51200;   const float* WT_e2h = g_wt + 67584;
    const float* WT_d0i = g_wt + 83968;   const float* WT_d0h = g_wt + 102400;
    const float* WT_d1i = g_wt + 118784;  const float* WT_d1h = g_wt + 135168;
    const float* WT_d2i = g_wt + 151552;  const float* WT_d2h = g_wt + 167936;

    float* h0 = s_hs;
    float* h1 = s_hs + HH * RP;
    float* h2 = s_hs + 2 * HH * RP;
    float* c0 = s_cs;
    float* c1 = s_cs + HH * RP;
    float* c2 = s_cs + 2 * HH * RP;

    int xr = tid >> 3, xk = tid & 7;      // x staging: 32 rows x 8 dims = 256 threads

    // ---------------- encoder ----------------
    for (int t = 0; t < TT; t++) {
        s_x[xk * RP + xr] = enc_x[(size_t)(b0 + xr) * TT * DD + t * DD + xk];
        __syncthreads();
        layer_step(WT_e0i, DD, s_x, nullptr, nullptr, WT_e0h, h0, eb0, s_g, h0, c0, nullptr, tid);
        layer_step(WT_e1i, HH, h0,  nullptr, nullptr, WT_e1h, h1, eb1, s_g, h1, c1, nullptr, tid);
        layer_step(WT_e2i, HH, h1,  nullptr, nullptr, WT_e2h, h2, eb2, s_g, h2, c2, nullptr, tid);
    }

    // ---------------- decoder ----------------
    // states carry over from encoder; y_prev starts at 0 (s_y zeroed at init)
    int pr = tid >> 3, pd = tid & 7;      // pred: 32 rows x 8 outputs
    for (int t = 0; t < TT; t++) {
        s_x[xk * RP + xr] = dec_x[(size_t)(b0 + xr) * TT * DD + t * DD + xk];
        __syncthreads();
        // layer0 input = concat([x_t (8), y_prev (64)]); WT_d0i rows 0..7 -> x, 8..71 -> y
        layer_step(WT_d0i, DD, s_x, WT_d0i + DD * 256, s_y, WT_d0h, h0, db0, s_g, h0, c0, nullptr, tid);
        layer_step(WT_d1i, HH, h0,  nullptr, nullptr,  WT_d1h, h1, db1, s_g, h1, c1, nullptr, tid);
        // layer2 update also refreshes y_prev for next step
        layer_step(WT_d2i, HH, h1,  nullptr, nullptr,  WT_d2h, h2, db2, s_g, h2, c2, s_y, tid);

        // pred = h2 @ fcW^T + fcb
        float a = s_fc[512 + pd];
        #pragma unroll 8
        for (int u = 0; u < HH; u++)
            a = fmaf(s_fc[u * 8 + pd], h2[u * RP + pr], a);
        out[(size_t)(b0 + pr) * TT * DD + t * DD + pd] = a;
        // no sync needed here: next iteration's s_x store + sync orders everything
    }
}

extern "C" void kernel_launch(void* const* d_in, const int* in_sizes, int n_in,
                              void* d_out, int out_size) {
    const float* enc_x = (const float*)d_in[0];
    const float* dec_x = (const float*)d_in[1];

    // Transpose all 12 weight matrices into g_wt (runs every launch; graph-capturable)
    struct TW { int src; int off; int cols; };
    const TW tw[12] = {
        { 2,      0,  8}, { 3,   2048, 64}, { 5,  18432, 64},
        { 6,  34816, 64}, { 8,  51200, 64}, { 9,  67584, 64},
        {11,  83968, 72}, {12, 102400, 64}, {14, 118784, 64},
        {15, 135168, 64}, {17, 151552, 64}, {18, 167936, 64}
    };
    for (int i = 0; i < 12; i++) {
        int n = tw[i].cols * 256;
        transpose_w<<<(n + 255) / 256, 256>>>((const float*)d_in[tw[i].src],
                                              tw[i].off, tw[i].cols);
    }

    size_t smem = (size_t)(3 * HH * RP * 2 + HH * RP + DD * RP + R * 256 + 520) * sizeof(float);
    cudaFuncSetAttribute(lstm_main, cudaFuncAttributeMaxDynamicSharedMemorySize, (int)smem);

    lstm_main<<<TB / R, NT, smem>>>(
        enc_x, dec_x,
        (const float*)d_in[4],  (const float*)d_in[7],  (const float*)d_in[10],
        (const float*)d_in[13], (const float*)d_in[16], (const float*)d_in[19],
        (const float*)d_in[20], (const float*)d_in[21],
        (float*)d_out);
}

// round 3
// speedup vs baseline: 1.1237x; 1.1237x over previous
#include <cuda_runtime.h>

// Problem constants
#define TB 8192   // batch
#define TT 512    // seq len
#define DD 8      // input size
#define HH 64     // hidden
#define R  32     // batch rows per block
#define RP 36     // padded row stride (floats): 144B, 16B aligned
#define NT 256    // threads per block (one per gate)

// Transposed-weight scratch: [k][256] layouts for all 12 matrices, contiguous.
// offsets (floats): e0i@0(8x256) e0h@2048 e1i@18432 e1h@34816 e2i@51200 e2h@67584
//                   d0i@83968(72x256) d0h@102400 d1i@118784 d1h@135168 d2i@151552 d2h@167936
#define WT_TOTAL 184320
__device__ float g_wt[WT_TOTAL];

struct WSrcs { const float* p[12]; };
__constant__ int c_woff[13] = {0, 2048, 18432, 34816, 51200, 67584, 83968,
                               102400, 118784, 135168, 151552, 167936, 184320};

__global__ void transpose_all(WSrcs ws) {
    int idx = blockIdx.x * blockDim.x + threadIdx.x;
    if (idx >= WT_TOTAL) return;
    int seg = 0;
    #pragma unroll
    for (int i = 1; i < 12; i++) seg += (idx >= c_woff[i]);
    int off  = c_woff[seg];
    int cols = (c_woff[seg + 1] - off) >> 8;
    int k = (idx - off) >> 8;
    int j = idx & 255;
    g_wt[idx] = ws.p[seg][j * cols + k];
}

// ---- fast transcendentals (MUFU.TANH) ----
__device__ __forceinline__ float tanh_fast(float x) {
    float y;
    asm("tanh.approx.f32 %0, %1;" : "=f"(y) : "f"(x));
    return y;
}
__device__ __forceinline__ float sig_fast(float x) {
    return fmaf(0.5f, tanh_fast(0.5f * x), 0.5f);
}

// ---- packed f32x2 helpers ----
__device__ __forceinline__ unsigned long long pack2(float w) {
    unsigned long long p;
    asm("mov.b64 %0, {%1, %1};" : "=l"(p) : "f"(w));
    return p;
}
__device__ __forceinline__ void fma2(unsigned long long& acc, unsigned long long a,
                                     unsigned long long b) {
    asm("fma.rn.f32x2 %0, %1, %2, %0;" : "+l"(acc) : "l"(a), "l"(b));
}

// acc2[q] (pair of batch rows 2q,2q+1) += sum_k WT[k][j] * buf[k][2q..2q+1]
__device__ __forceinline__ void gemv2(unsigned long long acc2[16],
                                      const float* __restrict__ WT, int K,
                                      const float* __restrict__ buf, int j) {
    #pragma unroll 4
    for (int k = 0; k < K; k++) {
        unsigned long long wp = pack2(WT[k * 256 + j]);   // coalesced LDG.32
        const ulonglong2* xp = (const ulonglong2*)(buf + k * RP);  // smem bcast
        #pragma unroll
        for (int q = 0; q < 8; q++) {
            ulonglong2 v = xp[q];                          // LDS.128 -> 4 rows
            fma2(acc2[2 * q],     wp, v.x);
            fma2(acc2[2 * q + 1], wp, v.y);
        }
    }
}

__device__ __forceinline__ void update_states(const float* __restrict__ s_g,
                                              float* __restrict__ h_st,
                                              float* __restrict__ c_st,
                                              float* __restrict__ y_copy,
                                              int tid) {
    int u  = tid & 63;
    int r0 = (tid >> 6) * 8;
    #pragma unroll
    for (int rr = 0; rr < 8; rr++) {
        int r = r0 + rr;
        const float* gr = s_g + r * 256;
        float gi = gr[u];
        float gf = gr[64 + u];
        float gg = gr[128 + u];
        float go = gr[192 + u];
        float c = c_st[u * RP + r];
        c = sig_fast(gf) * c + sig_fast(gi) * tanh_fast(gg);
        float h = sig_fast(go) * tanh_fast(c);
        c_st[u * RP + r] = c;
        h_st[u * RP + r] = h;
        if (y_copy) y_copy[u * RP + r] = h;
    }
}

// One LSTM layer for one timestep.
__device__ __forceinline__ void layer_step(const float* __restrict__ WTi, int Ki,
                                           const float* __restrict__ inbuf,
                                           const float* __restrict__ WTi2,
                                           const float* __restrict__ inbuf2,
                                           const float* __restrict__ WTh,
                                           const float* __restrict__ hbuf,
                                           const float* __restrict__ bias,
                                           float* __restrict__ s_g,
                                           float* __restrict__ h_st,
                                           float* __restrict__ c_st,
                                           float* __restrict__ y_copy,
                                           int tid) {
    unsigned long long acc2[16];
    unsigned long long bj = pack2(bias[tid]);
    #pragma unroll
    for (int q = 0; q < 16; q++) acc2[q] = bj;
    gemv2(acc2, WTi, Ki, inbuf, tid);
    if (inbuf2) gemv2(acc2, WTi2, HH, inbuf2, tid);
    gemv2(acc2, WTh, HH, hbuf, tid);
    #pragma unroll
    for (int q = 0; q < 16; q++) {
        float lo, hi;
        asm("mov.b64 {%0, %1}, %2;" : "=f"(lo), "=f"(hi) : "l"(acc2[q]));
        s_g[(2 * q)     * 256 + tid] = lo;   // coalesced STS
        s_g[(2 * q + 1) * 256 + tid] = hi;
    }
    __syncthreads();
    update_states(s_g, h_st, c_st, y_copy, tid);
    __syncthreads();
}

__global__ __launch_bounds__(NT, 2)
void lstm_main(const float* __restrict__ enc_x, const float* __restrict__ dec_x,
               const float* __restrict__ eb0, const float* __restrict__ eb1,
               const float* __restrict__ eb2,
               const float* __restrict__ db0, const float* __restrict__ db1,
               const float* __restrict__ db2,
               const float* __restrict__ fcW, const float* __restrict__ fcb,
               float* __restrict__ out) {
    extern __shared__ float sm[];
    float* s_hs = sm;                     // 3 * 64 * RP
    float* s_cs = s_hs + 3 * HH * RP;     // 3 * 64 * RP
    float* s_y  = s_cs + 3 * HH * RP;     // 64 * RP (decoder y_prev)
    float* s_x  = s_y + HH * RP;          // 8 * RP  (x_t staging)
    float* s_g  = s_x + DD * RP;          // 32 * 256 (gates [r][j])
    float* s_fc = s_g + R * 256;          // 64*8 fcW^T + 8 fcb

    int tid = threadIdx.x;
    int b0  = blockIdx.x * R;

    for (int i = tid; i < 3 * HH * RP * 2 + HH * RP; i += NT) sm[i] = 0.f;
    for (int i = tid; i < DD * HH; i += NT) {
        int u = i >> 3, d = i & 7;
        s_fc[u * 8 + d] = fcW[d * HH + u];
    }
    if (tid < DD) s_fc[512 + tid] = fcb[tid];
    __syncthreads();

    const float* WT_e0i = g_wt;           const float* WT_e0h = g_wt + 2048;
    const float* WT_e1i = g_wt + 18432;   const float* WT_e1h = g_wt + 34816;
    const float* WT_e2i = g_wt + 51200;   const float* WT_e2h = g_wt + 67584;
    const float* WT_d0i = g_wt + 83968;   const float* WT_d0h = g_wt + 102400;
    const float* WT_d1i = g_wt + 118784;  const float* WT_d1h = g_wt + 135168;
    const float* WT_d2i = g_wt + 151552;  const float* WT_d2h = g_wt + 167936;

    float* h0 = s_hs;
    float* h1 = s_hs + HH * RP;
    float* h2 = s_hs + 2 * HH * RP;
    float* c0 = s_cs;
    float* c1 = s_cs + HH * RP;
    float* c2 = s_cs + 2 * HH * RP;

    int xr = tid >> 3, xk = tid & 7;

    // ---------------- encoder ----------------
    for (int t = 0; t < TT; t++) {
        s_x[xk * RP + xr] = enc_x[(size_t)(b0 + xr) * TT * DD + t * DD + xk];
        __syncthreads();
        layer_step(WT_e0i, DD, s_x, nullptr, nullptr, WT_e0h, h0, eb0, s_g, h0, c0, nullptr, tid);
        layer_step(WT_e1i, HH, h0,  nullptr, nullptr, WT_e1h, h1, eb1, s_g, h1, c1, nullptr, tid);
        layer_step(WT_e2i, HH, h1,  nullptr, nullptr, WT_e2h, h2, eb2, s_g, h2, c2, nullptr, tid);
    }

    // ---------------- decoder ----------------
    int pr = tid >> 3, pd = tid & 7;
    for (int t = 0; t < TT; t++) {
        s_x[xk * RP + xr] = dec_x[(size_t)(b0 + xr) * TT * DD + t * DD + xk];
        __syncthreads();
        // layer0 input = concat([x_t (8), y_prev (64)])
        layer_step(WT_d0i, DD, s_x, WT_d0i + DD * 256, s_y, WT_d0h, h0, db0, s_g, h0, c0, nullptr, tid);
        layer_step(WT_d1i, HH, h0,  nullptr, nullptr,  WT_d1h, h1, db1, s_g, h1, c1, nullptr, tid);
        layer_step(WT_d2i, HH, h1,  nullptr, nullptr,  WT_d2h, h2, db2, s_g, h2, c2, s_y, tid);

        // pred = h2 @ fcW^T + fcb
        float a = s_fc[512 + pd];
        #pragma unroll 8
        for (int u = 0; u < HH; u++)
            a = fmaf(s_fc[u * 8 + pd], h2[u * RP + pr], a);
        out[(size_t)(b0 + pr) * TT * DD + t * DD + pd] = a;
        // next iteration's s_x store + sync orders everything
    }
}

extern "C" void kernel_launch(void* const* d_in, const int* in_sizes, int n_in,
                              void* d_out, int out_size) {
    const float* enc_x = (const float*)d_in[0];
    const float* dec_x = (const float*)d_in[1];

    // One fused transpose launch (also makes ncu -s 5 land on lstm_main)
    WSrcs ws;
    const int src_idx[12] = {2, 3, 5, 6, 8, 9, 11, 12, 14, 15, 17, 18};
    for (int i = 0; i < 12; i++) ws.p[i] = (const float*)d_in[src_idx[i]];
    transpose_all<<<(WT_TOTAL + 255) / 256, 256>>>(ws);

    size_t smem = (size_t)(3 * HH * RP * 2 + HH * RP + DD * RP + R * 256 + 520) * sizeof(float);
    cudaFuncSetAttribute(lstm_main, cudaFuncAttributeMaxDynamicSharedMemorySize, (int)smem);

    lstm_main<<<TB / R, NT, smem>>>(
        enc_x, dec_x,
        (const float*)d_in[4],  (const float*)d_in[7],  (const float*)d_in[10],
        (const float*)d_in[13], (const float*)d_in[16], (const float*)d_in[19],
        (const float*)d_in[20], (const float*)d_in[21],
        (float*)d_out);
}

// round 4
// speedup vs baseline: 1.4775x; 1.3149x over previous
#include <cuda_runtime.h>

#define TB 8192   // batch
#define TT 512    // seq len
#define DD 8      // input size
#define HH 64     // hidden
#define R  32     // batch rows per block
#define RP 32     // row stride (floats) — conflict-free under 4x8 tile access
#define NT 256    // threads: 64 units x 4 row-groups

// Gate-interleaved transposed weights: WTg[k][u][gate], gate in {i,f,g,o}.
// offsets (floats): e0i@0(8k) e0h@2048 e1i@18432 e1h@34816 e2i@51200 e2h@67584
//                   d0i@83968(72k: x 0..7, y 8..71) d0h@102400 d1i@118784
//                   d1h@135168 d2i@151552 d2h@167936
#define WT_TOTAL 184320
__device__ float g_wt[WT_TOTAL];

struct WSrcs { const float* p[12]; };
__constant__ int c_woff[13] = {0, 2048, 18432, 34816, 51200, 67584, 83968,
                               102400, 118784, 135168, 151552, 167936, 184320};

__global__ void transpose_all(WSrcs ws) {
    int idx = blockIdx.x * blockDim.x + threadIdx.x;
    if (idx >= WT_TOTAL) return;
    int seg = 0;
    #pragma unroll
    for (int i = 1; i < 12; i++) seg += (idx >= c_woff[i]);
    int off  = c_woff[seg];
    int cols = (c_woff[seg + 1] - off) >> 8;
    int pos = idx - off;
    int k = pos >> 8, rem = pos & 255, u = rem >> 2, g = rem & 3;
    g_wt[idx] = ws.p[seg][(g * HH + u) * cols + k];
}

// ---- fast transcendentals (MUFU.TANH) ----
__device__ __forceinline__ float tanh_fast(float x) {
    float y;
    asm("tanh.approx.f32 %0, %1;" : "=f"(y) : "f"(x));
    return y;
}
__device__ __forceinline__ float sig_fast(float x) {
    return fmaf(0.5f, tanh_fast(0.5f * x), 0.5f);
}

// ---- packed f32x2 helpers ----
__device__ __forceinline__ unsigned long long pack2(float w) {
    unsigned long long p;
    asm("mov.b64 %0, {%1, %1};" : "=l"(p) : "f"(w));
    return p;
}
__device__ __forceinline__ void fma2(unsigned long long& acc, unsigned long long a,
                                     unsigned long long b) {
    asm("fma.rn.f32x2 %0, %1, %2, %0;" : "+l"(acc) : "l"(a), "l"(b));
}
__device__ __forceinline__ void unpack2(unsigned long long p, float& lo, float& hi) {
    asm("mov.b64 {%0, %1}, %2;" : "=f"(lo), "=f"(hi) : "l"(p));
}

// acc[g*4+q] += WTg[k][u][g] * buf[k][rg*8 + 2q..2q+1]   (f32x2 over row pairs)
__device__ __forceinline__ void gemv4(unsigned long long acc[16],
                                      const float* __restrict__ WTg, int K,
                                      const float* __restrict__ buf,
                                      int u, int rg) {
    #pragma unroll 4
    for (int k = 0; k < K; k++) {
        float4 w4 = *(const float4*)(WTg + k * 256 + u * 4);   // LDG.128, 1 line/warp
        unsigned long long wi = pack2(w4.x), wf = pack2(w4.y);
        unsigned long long wg = pack2(w4.z), wo = pack2(w4.w);
        const ulonglong2* xp = (const ulonglong2*)(buf + k * RP + rg * 8);
        ulonglong2 v01 = xp[0];                                 // rows 0..3 of group
        ulonglong2 v23 = xp[1];                                 // rows 4..7
        fma2(acc[0],  wi, v01.x); fma2(acc[1],  wi, v01.y);
        fma2(acc[2],  wi, v23.x); fma2(acc[3],  wi, v23.y);
        fma2(acc[4],  wf, v01.x); fma2(acc[5],  wf, v01.y);
        fma2(acc[6],  wf, v23.x); fma2(acc[7],  wf, v23.y);
        fma2(acc[8],  wg, v01.x); fma2(acc[9],  wg, v01.y);
        fma2(acc[10], wg, v23.x); fma2(acc[11], wg, v23.y);
        fma2(acc[12], wo, v01.x); fma2(acc[13], wo, v01.y);
        fma2(acc[14], wo, v23.x); fma2(acc[15], wo, v23.y);
    }
}

// One LSTM layer step: gemv -> register state update -> h store -> sync.
__device__ __forceinline__ void layer_step(const float* __restrict__ WTi, int Ki,
                                           const float* __restrict__ inbuf,
                                           const float* __restrict__ WTi2,
                                           const float* __restrict__ inbuf2,
                                           const float* __restrict__ WTh,
                                           const float* __restrict__ hprev,
                                           const float* __restrict__ bias,
                                           float* __restrict__ c_reg,
                                           float* __restrict__ hout,
                                           int u, int rg) {
    unsigned long long acc[16];
    {
        unsigned long long bi = pack2(bias[u]);
        unsigned long long bf = pack2(bias[HH + u]);
        unsigned long long bg = pack2(bias[2 * HH + u]);
        unsigned long long bo = pack2(bias[3 * HH + u]);
        acc[0] = acc[1] = acc[2] = acc[3] = bi;
        acc[4] = acc[5] = acc[6] = acc[7] = bf;
        acc[8] = acc[9] = acc[10] = acc[11] = bg;
        acc[12] = acc[13] = acc[14] = acc[15] = bo;
    }
    gemv4(acc, WTi, Ki, inbuf, u, rg);
    if (inbuf2) gemv4(acc, WTi2, HH, inbuf2, u, rg);
    gemv4(acc, WTh, HH, hprev, u, rg);

    float hv[8];
    #pragma unroll
    for (int q = 0; q < 4; q++) {
        float i0, i1, f0, f1, g0, g1, o0, o1;
        unpack2(acc[q],      i0, i1);
        unpack2(acc[4 + q],  f0, f1);
        unpack2(acc[8 + q],  g0, g1);
        unpack2(acc[12 + q], o0, o1);
        float c;
        c = c_reg[2 * q];
        c = sig_fast(f0) * c + sig_fast(i0) * tanh_fast(g0);
        hv[2 * q] = sig_fast(o0) * tanh_fast(c);
        c_reg[2 * q] = c;
        c = c_reg[2 * q + 1];
        c = sig_fast(f1) * c + sig_fast(i1) * tanh_fast(g1);
        hv[2 * q + 1] = sig_fast(o1) * tanh_fast(c);
        c_reg[2 * q + 1] = c;
    }
    float4* hp = (float4*)(hout + u * RP + rg * 8);
    hp[0] = make_float4(hv[0], hv[1], hv[2], hv[3]);
    hp[1] = make_float4(hv[4], hv[5], hv[6], hv[7]);
    __syncthreads();
}

__global__ __launch_bounds__(NT, 2)
void lstm_main(const float* __restrict__ enc_x, const float* __restrict__ dec_x,
               const float* __restrict__ eb0, const float* __restrict__ eb1,
               const float* __restrict__ eb2,
               const float* __restrict__ db0, const float* __restrict__ db1,
               const float* __restrict__ db2,
               const float* __restrict__ fcW, const float* __restrict__ fcb,
               float* __restrict__ out) {
    extern __shared__ float sm[];
    float* s_h  = sm;                     // [2 parity][3 layer][64][RP] = 12288 floats
    float* s_x  = s_h + 2 * 3 * HH * RP;  // [8][RP]
    float* s_fc = s_x + DD * RP;          // 512 fcW^T + 8 fcb

    int tid = threadIdx.x;
    int b0  = blockIdx.x * R;
    int u = tid >> 2, rg = tid & 3;       // gemv tile coords
    int xr = tid >> 3, xk = tid & 7;      // x staging coords
    int pr = tid >> 3, pd = tid & 7;      // fc output coords

    for (int i = tid; i < 2 * 3 * HH * RP; i += NT) s_h[i] = 0.f;
    for (int i = tid; i < DD * HH; i += NT) {
        int uu = i >> 3, d = i & 7;
        s_fc[uu * 8 + d] = fcW[d * HH + uu];
    }
    if (tid < DD) s_fc[512 + tid] = fcb[tid];
    __syncthreads();

    const float* WT_e0i = g_wt;           const float* WT_e0h = g_wt + 2048;
    const float* WT_e1i = g_wt + 18432;   const float* WT_e1h = g_wt + 34816;
    const float* WT_e2i = g_wt + 51200;   const float* WT_e2h = g_wt + 67584;
    const float* WT_d0i = g_wt + 83968;   const float* WT_d0h = g_wt + 102400;
    const float* WT_d1i = g_wt + 118784;  const float* WT_d1h = g_wt + 135168;
    const float* WT_d2i = g_wt + 151552;  const float* WT_d2h = g_wt + 167936;

    float c0[8], c1[8], c2[8];
    #pragma unroll
    for (int i = 0; i < 8; i++) c0[i] = c1[i] = c2[i] = 0.f;

    const int LSZ = HH * RP;              // 2048 floats per layer buffer
    int p = 0;

    // ---------------- encoder ----------------
    for (int t = 0; t < TT; t++) {
        float* hc = s_h + p * 3 * LSZ;          // write parity
        float* hv = s_h + (p ^ 1) * 3 * LSZ;    // read parity (recurrent)
        s_x[xk * RP + xr] = enc_x[(size_t)(b0 + xr) * TT * DD + t * DD + xk];
        __syncthreads();
        layer_step(WT_e0i, DD, s_x, nullptr, nullptr, WT_e0h, hv,           eb0, c0, hc,           u, rg);
        layer_step(WT_e1i, HH, hc,  nullptr, nullptr, WT_e1h, hv + LSZ,     eb1, c1, hc + LSZ,     u, rg);
        layer_step(WT_e2i, HH, hc + LSZ, nullptr, nullptr, WT_e2h, hv + 2 * LSZ, eb2, c2, hc + 2 * LSZ, u, rg);
        p ^= 1;
    }

    // ---------------- decoder ----------------
    for (int t = 0; t < TT; t++) {
        float* hc = s_h + p * 3 * LSZ;
        float* hv = s_h + (p ^ 1) * 3 * LSZ;
        s_x[xk * RP + xr] = dec_x[(size_t)(b0 + xr) * TT * DD + t * DD + xk];
        __syncthreads();
        // layer0 input = concat([x_t, y_prev]); y_prev = prev-parity h2 (zero at t=0 -> skip)
        const float* ybuf = (t > 0) ? (hv + 2 * LSZ) : nullptr;
        layer_step(WT_d0i, DD, s_x, WT_d0i + DD * 256, ybuf, WT_d0h, hv,       db0, c0, hc,           u, rg);
        layer_step(WT_d1i, HH, hc,  nullptr, nullptr,  WT_d1h, hv + LSZ,       db1, c1, hc + LSZ,     u, rg);
        layer_step(WT_d2i, HH, hc + LSZ, nullptr, nullptr, WT_d2h, hv + 2 * LSZ, db2, c2, hc + 2 * LSZ, u, rg);

        // pred = h2 @ fcW^T + fcb
        const float* h2 = hc + 2 * LSZ;
        float a = s_fc[512 + pd];
        #pragma unroll 8
        for (int uu = 0; uu < HH; uu++)
            a = fmaf(s_fc[uu * 8 + pd], h2[uu * RP + pr], a);
        out[(size_t)(b0 + pr) * TT * DD + t * DD + pd] = a;
        p ^= 1;
        // next step's s_x store + sync orders everything
    }
}

extern "C" void kernel_launch(void* const* d_in, const int* in_sizes, int n_in,
                              void* d_out, int out_size) {
    const float* enc_x = (const float*)d_in[0];
    const float* dec_x = (const float*)d_in[1];

    WSrcs ws;
    const int src_idx[12] = {2, 3, 5, 6, 8, 9, 11, 12, 14, 15, 17, 18};
    for (int i = 0; i < 12; i++) ws.p[i] = (const float*)d_in[src_idx[i]];
    transpose_all<<<(WT_TOTAL + 255) / 256, 256>>>(ws);

    size_t smem = (size_t)(2 * 3 * HH * RP + DD * RP + 520) * sizeof(float);
    cudaFuncSetAttribute(lstm_main, cudaFuncAttributeMaxDynamicSharedMemorySize, (int)smem);

    lstm_main<<<TB / R, NT, smem>>>(
        enc_x, dec_x,
        (const float*)d_in[4],  (const float*)d_in[7],  (const float*)d_in[10],
        (const float*)d_in[13], (const float*)d_in[16], (const float*)d_in[19],
        (const float*)d_in[20], (const float*)d_in[21],
        (float*)d_out);
}

// round 5
// speedup vs baseline: 1.5263x; 1.0330x over previous
#include <cuda_runtime.h>

#define TB 8192   // batch
#define TT 512    // seq len
#define DD 8      // input size
#define HH 64     // hidden
#define R  32     // batch rows per block
#define RP 36     // row stride (floats): 144B, 16B-aligned, bank-stride 4
#define NT 256    // threads: u = tid&63 (unit), rg = tid>>6 (row group)

// Gate-interleaved transposed weights WTg[k][u][gate] + interleaved biases.
// offsets (floats):
//  e0i@0(8k) e0h@2048 e1i@18432 e1h@34816 e2i@51200 e2h@67584
//  d0i@83968(72k) d0h@102400 d1i@118784 d1h@135168 d2i@151552 d2h@167936
//  eb0@184320 eb1@184576 eb2@184832 db0@185088 db1@185344 db2@185600
#define WT_TOTAL 185856
__device__ float g_wt[WT_TOTAL];

struct WSrcs { const float* p[18]; };
__constant__ int c_woff[19] = {0, 2048, 18432, 34816, 51200, 67584, 83968,
                               102400, 118784, 135168, 151552, 167936, 184320,
                               184576, 184832, 185088, 185344, 185600, 185856};

__global__ void transpose_all(WSrcs ws) {
    int idx = blockIdx.x * blockDim.x + threadIdx.x;
    if (idx >= WT_TOTAL) return;
    int seg = 0;
    #pragma unroll
    for (int i = 1; i < 18; i++) seg += (idx >= c_woff[i]);
    int off  = c_woff[seg];
    int cols = (c_woff[seg + 1] - off) >> 8;   // 1 for bias segments
    int pos = idx - off;
    int k = pos >> 8, rem = pos & 255, u = rem >> 2, g = rem & 3;
    g_wt[idx] = ws.p[seg][(g * HH + u) * cols + k];
}

// ---- fast transcendentals (MUFU.TANH) ----
__device__ __forceinline__ float tanh_fast(float x) {
    float y;
    asm("tanh.approx.f32 %0, %1;" : "=f"(y) : "f"(x));
    return y;
}
__device__ __forceinline__ float sig_fast(float x) {
    return fmaf(0.5f, tanh_fast(0.5f * x), 0.5f);
}

// ---- packed f32x2 helpers ----
__device__ __forceinline__ unsigned long long pack2(float w) {
    unsigned long long p;
    asm("mov.b64 %0, {%1, %1};" : "=l"(p) : "f"(w));
    return p;
}
__device__ __forceinline__ void fma2(unsigned long long& acc, unsigned long long a,
                                     unsigned long long b) {
    asm("fma.rn.f32x2 %0, %1, %2, %0;" : "+l"(acc) : "l"(a), "l"(b));
}
__device__ __forceinline__ void unpack2(unsigned long long p, float& lo, float& hi) {
    asm("mov.b64 {%0, %1}, %2;" : "=f"(lo), "=f"(hi) : "l"(p));
}

// acc[g*4+q] += WTg[k][u][g] * buf[k][rg*8 + 2q..2q+1]
// LDS are full-warp broadcasts (rg constant per warp); LDG is 512B contiguous/warp.
__device__ __forceinline__ void gemv4(unsigned long long acc[16],
                                      const float* __restrict__ WTg, int K,
                                      const float* __restrict__ buf,
                                      int u, int rg) {
    #pragma unroll 4
    for (int k = 0; k < K; k++) {
        float4 w4 = *(const float4*)(WTg + k * 256 + u * 4);
        unsigned long long wi = pack2(w4.x), wf = pack2(w4.y);
        unsigned long long wg = pack2(w4.z), wo = pack2(w4.w);
        const ulonglong2* xp = (const ulonglong2*)(buf + k * RP + rg * 8);
        ulonglong2 v01 = xp[0];                 // broadcast LDS.128
        ulonglong2 v23 = xp[1];                 // broadcast LDS.128
        fma2(acc[0],  wi, v01.x); fma2(acc[1],  wi, v01.y);
        fma2(acc[2],  wi, v23.x); fma2(acc[3],  wi, v23.y);
        fma2(acc[4],  wf, v01.x); fma2(acc[5],  wf, v01.y);
        fma2(acc[6],  wf, v23.x); fma2(acc[7],  wf, v23.y);
        fma2(acc[8],  wg, v01.x); fma2(acc[9],  wg, v01.y);
        fma2(acc[10], wg, v23.x); fma2(acc[11], wg, v23.y);
        fma2(acc[12], wo, v01.x); fma2(acc[13], wo, v01.y);
        fma2(acc[14], wo, v23.x); fma2(acc[15], wo, v23.y);
    }
}

// One LSTM layer step: gemv -> register state update -> h store -> sync.
__device__ __forceinline__ void layer_step(const float* __restrict__ WTi, int Ki,
                                           const float* __restrict__ inbuf,
                                           const float* __restrict__ WTi2,
                                           const float* __restrict__ inbuf2,
                                           const float* __restrict__ WTh,
                                           const float* __restrict__ hprev,
                                           const float* __restrict__ Bint,
                                           float* __restrict__ c_reg,
                                           float* __restrict__ hout,
                                           int u, int rg) {
    unsigned long long acc[16];
    {
        float4 b4 = *(const float4*)(Bint + u * 4);   // interleaved bias, 1 LDG.128
        unsigned long long bi = pack2(b4.x), bf = pack2(b4.y);
        unsigned long long bg = pack2(b4.z), bo = pack2(b4.w);
        acc[0] = acc[1] = acc[2] = acc[3] = bi;
        acc[4] = acc[5] = acc[6] = acc[7] = bf;
        acc[8] = acc[9] = acc[10] = acc[11] = bg;
        acc[12] = acc[13] = acc[14] = acc[15] = bo;
    }
    gemv4(acc, WTi, Ki, inbuf, u, rg);
    if (inbuf2) gemv4(acc, WTi2, HH, inbuf2, u, rg);
    gemv4(acc, WTh, HH, hprev, u, rg);

    float hv[8];
    #pragma unroll
    for (int q = 0; q < 4; q++) {
        float i0, i1, f0, f1, g0, g1, o0, o1;
        unpack2(acc[q],      i0, i1);
        unpack2(acc[4 + q],  f0, f1);
        unpack2(acc[8 + q],  g0, g1);
        unpack2(acc[12 + q], o0, o1);
        float c;
        c = c_reg[2 * q];
        c = sig_fast(f0) * c + sig_fast(i0) * tanh_fast(g0);
        hv[2 * q] = sig_fast(o0) * tanh_fast(c);
        c_reg[2 * q] = c;
        c = c_reg[2 * q + 1];
        c = sig_fast(f1) * c + sig_fast(i1) * tanh_fast(g1);
        hv[2 * q + 1] = sig_fast(o1) * tanh_fast(c);
        c_reg[2 * q + 1] = c;
    }
    float4* hp = (float4*)(hout + u * RP + rg * 8);
    hp[0] = make_float4(hv[0], hv[1], hv[2], hv[3]);
    hp[1] = make_float4(hv[4], hv[5], hv[6], hv[7]);
    __syncthreads();
}

__global__ __launch_bounds__(NT, 2)
void lstm_main(const float* __restrict__ enc_x, const float* __restrict__ dec_x,
               const float* __restrict__ fcW, const float* __restrict__ fcb,
               float* __restrict__ out) {
    extern __shared__ float sm[];
    float* s_h  = sm;                     // [2 parity][3 layer][64][RP]
    float* s_x  = s_h + 2 * 3 * HH * RP;  // [8][RP]
    float* s_fc = s_x + DD * RP;          // 512 fcW^T + 8 fcb

    int tid = threadIdx.x;
    int b0  = blockIdx.x * R;
    int u = tid & 63, rg = tid >> 6;      // gemv tile coords (rg constant per warp)
    int xr = tid >> 3, xk = tid & 7;      // x staging coords
    int pr = tid >> 3, pd = tid & 7;      // fc output coords

    for (int i = tid; i < 2 * 3 * HH * RP; i += NT) s_h[i] = 0.f;
    for (int i = tid; i < DD * HH; i += NT) {
        int uu = i >> 3, d = i & 7;
        s_fc[uu * 8 + d] = fcW[d * HH + uu];
    }
    if (tid < DD) s_fc[512 + tid] = fcb[tid];
    __syncthreads();

    const float* WT_e0i = g_wt;           const float* WT_e0h = g_wt + 2048;
    const float* WT_e1i = g_wt + 18432;   const float* WT_e1h = g_wt + 34816;
    const float* WT_e2i = g_wt + 51200;   const float* WT_e2h = g_wt + 67584;
    const float* WT_d0i = g_wt + 83968;   const float* WT_d0h = g_wt + 102400;
    const float* WT_d1i = g_wt + 118784;  const float* WT_d1h = g_wt + 135168;
    const float* WT_d2i = g_wt + 151552;  const float* WT_d2h = g_wt + 167936;
    const float* B_e0 = g_wt + 184320;    const float* B_e1 = g_wt + 184576;
    const float* B_e2 = g_wt + 184832;    const float* B_d0 = g_wt + 185088;
    const float* B_d1 = g_wt + 185344;    const float* B_d2 = g_wt + 185600;

    float c0[8], c1[8], c2[8];
    #pragma unroll
    for (int i = 0; i < 8; i++) c0[i] = c1[i] = c2[i] = 0.f;

    const int LSZ = HH * RP;
    int p = 0;

    // ---------------- encoder ----------------
    for (int t = 0; t < TT; t++) {
        float* hc = s_h + p * 3 * LSZ;          // write parity
        float* hv = s_h + (p ^ 1) * 3 * LSZ;    // read parity
        s_x[xk * RP + xr] = enc_x[(size_t)(b0 + xr) * TT * DD + t * DD + xk];
        __syncthreads();
        layer_step(WT_e0i, DD, s_x,      nullptr, nullptr, WT_e0h, hv,           B_e0, c0, hc,           u, rg);
        layer_step(WT_e1i, HH, hc,       nullptr, nullptr, WT_e1h, hv + LSZ,     B_e1, c1, hc + LSZ,     u, rg);
        layer_step(WT_e2i, HH, hc + LSZ, nullptr, nullptr, WT_e2h, hv + 2 * LSZ, B_e2, c2, hc + 2 * LSZ, u, rg);
        p ^= 1;
    }

    // ---------------- decoder ----------------
    for (int t = 0; t < TT; t++) {
        float* hc = s_h + p * 3 * LSZ;
        float* hv = s_h + (p ^ 1) * 3 * LSZ;
        s_x[xk * RP + xr] = dec_x[(size_t)(b0 + xr) * TT * DD + t * DD + xk];
        __syncthreads();
        const float* ybuf = (t > 0) ? (hv + 2 * LSZ) : nullptr;   // y_prev = prev h2
        layer_step(WT_d0i, DD, s_x,      WT_d0i + DD * 256, ybuf, WT_d0h, hv,           B_d0, c0, hc,           u, rg);
        layer_step(WT_d1i, HH, hc,       nullptr, nullptr,  WT_d1h, hv + LSZ,     B_d1, c1, hc + LSZ,     u, rg);
        layer_step(WT_d2i, HH, hc + LSZ, nullptr, nullptr,  WT_d2h, hv + 2 * LSZ, B_d2, c2, hc + 2 * LSZ, u, rg);

        // pred = h2 @ fcW^T + fcb
        const float* h2 = hc + 2 * LSZ;
        float a = s_fc[512 + pd];
        #pragma unroll 8
        for (int uu = 0; uu < HH; uu++)
            a = fmaf(s_fc[uu * 8 + pd], h2[uu * RP + pr], a);
        out[(size_t)(b0 + pr) * TT * DD + t * DD + pd] = a;
        p ^= 1;
    }
}

extern "C" void kernel_launch(void* const* d_in, const int* in_sizes, int n_in,
                              void* d_out, int out_size) {
    const float* enc_x = (const float*)d_in[0];
    const float* dec_x = (const float*)d_in[1];

    WSrcs ws;
    const int src_idx[18] = {2, 3, 5, 6, 8, 9, 11, 12, 14, 15, 17, 18,
                             4, 7, 10, 13, 16, 19};   // 12 weights + 6 biases
    for (int i = 0; i < 18; i++) ws.p[i] = (const float*)d_in[src_idx[i]];
    transpose_all<<<(WT_TOTAL + 255) / 256, 256>>>(ws);

    size_t smem = (size_t)(2 * 3 * HH * RP + DD * RP + 520) * sizeof(float);
    cudaFuncSetAttribute(lstm_main, cudaFuncAttributeMaxDynamicSharedMemorySize, (int)smem);

    lstm_main<<<TB / R, NT, smem>>>(enc_x, dec_x,
                                    (const float*)d_in[20], (const float*)d_in[21],
                                    (float*)d_out);
}